// round 13
// baseline (speedup 1.0000x reference)
#include <cuda_runtime.h>
#include <cuda_fp16.h>
#include <stdint.h>

#define IN_F    768
#define HID     64
#define MTILE   256
#define THREADS 512          // 16 warps, one 16-row stripe each
#define NSTEP1  48           // 768/16 k-steps for layer 1 (= chunks)
#define NSTEP2  4            // 64/16 for layer 2
#define DEPTH   4            // cp.async ring depth
#define CHUNK_B 16384        // 256 rows x 16 K x 4B

// ---------------- device scratch (no allocations allowed) ----------------
__device__ float g_w1d[HID * IN_F];            // dense W1^T [n][k]
__device__ float g_w2d[HID * HID];             // dense W2^T [n][k]
__device__ uint2 g_w1m[NSTEP1 * 8 * 32];       // W1 B-fragments, main only (b0,b1)
__device__ uint4 g_w2f[NSTEP2 * 8 * 32];       // W2 B-fragments main+residual
__device__ float g_w3[HID];

static __device__ __forceinline__ void mma16816(float* d, const uint32_t* a,
                                                uint32_t b0, uint32_t b1) {
    asm volatile(
        "mma.sync.aligned.m16n8k16.row.col.f32.f16.f16.f32 "
        "{%0,%1,%2,%3}, {%4,%5,%6,%7}, {%8,%9}, {%0,%1,%2,%3};"
        : "+f"(d[0]), "+f"(d[1]), "+f"(d[2]), "+f"(d[3])
        : "r"(a[0]), "r"(a[1]), "r"(a[2]), "r"(a[3]), "r"(b0), "r"(b1));
}
static __device__ __forceinline__ uint32_t pkh(__half a, __half b) {
    __half2 h = __halves2half2(a, b);
    return *reinterpret_cast<uint32_t*>(&h);
}
static __device__ __forceinline__ uint32_t pk2(float2 v) {
    __half2 h = __floats2half2_rn(v.x, v.y);
    return *reinterpret_cast<uint32_t*>(&h);
}
static __device__ __forceinline__ void cp_async16(uint32_t daddr, const void* src, int srcsz) {
    asm volatile("cp.async.cg.shared.global [%0], [%1], 16, %2;"
                 :: "r"(daddr), "l"(src), "r"(srcsz) : "memory");
}
static __device__ __forceinline__ void cp_commit() {
    asm volatile("cp.async.commit_group;" ::: "memory");
}
template <int N>
static __device__ __forceinline__ void cp_wait() {
    asm volatile("cp.async.wait_group %0;" :: "n"(N) : "memory");
}

// ---------------- prep: zero -> scatter -> pack fragments ----------------
__global__ void zero_kernel() {
    const int t = blockIdx.x * blockDim.x + threadIdx.x;
    const int n = gridDim.x * blockDim.x;
    for (int i = t; i < HID * IN_F; i += n) g_w1d[i] = 0.f;
    for (int i = t; i < HID * HID;  i += n) g_w2d[i] = 0.f;
    for (int i = t; i < HID;        i += n) g_w3[i]  = 0.f;
}

__global__ void scatter_kernel(const int* __restrict__ idx1, const float* __restrict__ val1, int nnz1,
                               const int* __restrict__ idx2, const float* __restrict__ val2, int nnz2,
                               const int* __restrict__ idx3, const float* __restrict__ val3, int nnz3)
{
    const int t = blockIdx.x * blockDim.x + threadIdx.x;
    const int n = gridDim.x * blockDim.x;
    // idx layout [2,nnz]: rows then cols. dense is [n(col)][k(row)].
    for (int i = t; i < nnz1; i += n)
        atomicAdd(&g_w1d[idx1[nnz1 + i] * IN_F + idx1[i]], val1[i]);
    for (int i = t; i < nnz2; i += n)
        atomicAdd(&g_w2d[idx2[nnz2 + i] * HID + idx2[i]], val2[i]);
    for (int i = t; i < nnz3; i += n)
        atomicAdd(&g_w3[idx3[i]], val3[i]);
}

__global__ void pack_kernel() {
    const int tid = threadIdx.x;
    if (blockIdx.x < NSTEP1) {                 // one block per k-step of W1 (main only)
        const int s    = blockIdx.x;
        const int nb   = tid >> 5;
        const int lane = tid & 31;
        if (nb < 8) {
            const int k0 = s * 16 + (lane & 3) * 2;
            const int n  = nb * 8 + (lane >> 2);
            const float m0 = g_w1d[n * IN_F + k0];
            const float m1 = g_w1d[n * IN_F + k0 + 1];
            const float m2 = g_w1d[n * IN_F + k0 + 8];
            const float m3 = g_w1d[n * IN_F + k0 + 9];
            uint2 u;
            u.x = pkh(__float2half_rn(m0), __float2half_rn(m1));
            u.y = pkh(__float2half_rn(m2), __float2half_rn(m3));
            g_w1m[(s * 8 + nb) * 32 + lane] = u;
        }
    } else {                                   // last block packs all of W2 (main+resid)
        for (int j = tid; j < NSTEP2 * 8 * 32; j += 256) {
            const int s    = j >> 8;
            const int nb   = (j >> 5) & 7;
            const int lane = j & 31;
            const int k0 = s * 16 + (lane & 3) * 2;
            const int n  = nb * 8 + (lane >> 2);
            const float m0 = g_w2d[n * HID + k0];
            const float m1 = g_w2d[n * HID + k0 + 1];
            const float m2 = g_w2d[n * HID + k0 + 8];
            const float m3 = g_w2d[n * HID + k0 + 9];
            const __half h0 = __float2half_rn(m0), h1 = __float2half_rn(m1);
            const __half h2 = __float2half_rn(m2), h3 = __float2half_rn(m3);
            uint4 u;
            u.x = pkh(h0, h1);
            u.y = pkh(h2, h3);
            u.z = pkh(__float2half_rn(m0 - __half2float(h0)), __float2half_rn(m1 - __half2float(h1)));
            u.w = pkh(__float2half_rn(m2 - __half2float(h2)), __float2half_rn(m3 - __half2float(h3)));
            g_w2f[(s * 8 + nb) * 32 + lane] = u;
        }
    }
}

// ---------------------------------------------------------------------------
// Main kernel (R12 structure, R13 delta): 512 threads / 16 warps, each warp
// owns ONE 16-row stripe -> 32 accumulators/thread -> ~64 regs ->
// 2 CTAs x 16 warps = 32 warps/SM (2x latency hiding). Same 16B cp.async
// ring, one barrier per chunk, main-only W1, residual W2, register h1.
// ---------------------------------------------------------------------------
extern __shared__ __align__(16) unsigned char smem[];

__global__ __launch_bounds__(THREADS, 2)
void mma_kernel(const float* __restrict__ x,
                const float* __restrict__ b1,
                const float* __restrict__ b2,
                const float* __restrict__ b3,
                float* __restrict__ out, int batch)
{
    uint32_t sb;
    asm("{ .reg .u64 t; cvta.to.shared.u64 t, %1; cvt.u32.u64 %0, t; }" : "=r"(sb) : "l"(smem));
    const int tid  = threadIdx.x;
    const int w    = tid >> 5;          // 0..15, stripe index
    const int lane = tid & 31;
    const int row0 = blockIdx.x * MTILE;
    const bool full = (row0 + MTILE) <= batch;

    // ---- cp.async issue of one 16-K chunk: 16B copies, 2 per thread ----
    const int crow = tid >> 2;          // 0..127 (row within a 128-row pass)
    const int cu   = tid & 3;           // 16B unit within the 64B row piece
    auto issue = [&](int c) {
        const uint32_t dbase = sb + (uint32_t)(c & (DEPTH - 1)) * CHUNK_B;
        #pragma unroll
        for (int j = 0; j < 2; ++j) {
            const int row = j * 128 + crow;
            const int ok = (full || (row0 + row) < batch) ? 16 : 0;
            const float* src = x + (size_t)(row0 + row) * IN_F + c * 16 + cu * 4;
            cp_async16(dbase + (uint32_t)(row * 64 + cu * 16), src, ok);
        }
        cp_commit();
    };

    // A-fragment LDS geometry (verified ordering; one stripe)
    const uint32_t a0 = (uint32_t)((w * 16 + (lane >> 2)) * 64 + (lane & 3) * 8);

    float acc[32];
    #pragma unroll
    for (int i = 0; i < 32; ++i) acc[i] = 0.f;

    // ---- prologue: 3 chunks in flight ----
    issue(0); issue(1); issue(2);

    // ---- layer-1 mainloop over 48 chunks: ONE barrier per chunk ----
    #pragma unroll 1
    for (int c = 0; c < NSTEP1; ++c) {
        cp_wait<2>();                 // this thread's chunk-c copies landed
        __syncthreads();              // chunk-c visible; all warps done with c-1
        if (c + 3 < NSTEP1) issue(c + 3);   // refills slot (c-1)&3 — WAR-safe

        const uint32_t xb = sb + (uint32_t)(c & (DEPTH - 1)) * CHUNK_B;
        uint32_t af[4];
        {
            float2 v;
            asm volatile("ld.shared.v2.f32 {%0,%1}, [%2];" : "=f"(v.x), "=f"(v.y) : "r"(xb + a0));
            af[0] = pk2(v);
            asm volatile("ld.shared.v2.f32 {%0,%1}, [%2];" : "=f"(v.x), "=f"(v.y) : "r"(xb + a0 + 512));
            af[1] = pk2(v);
            asm volatile("ld.shared.v2.f32 {%0,%1}, [%2];" : "=f"(v.x), "=f"(v.y) : "r"(xb + a0 + 32));
            af[2] = pk2(v);
            asm volatile("ld.shared.v2.f32 {%0,%1}, [%2];" : "=f"(v.x), "=f"(v.y) : "r"(xb + a0 + 544));
            af[3] = pk2(v);
        }

        const uint2* wf = g_w1m + (size_t)c * 256 + lane;
        #pragma unroll
        for (int nb = 0; nb < 8; ++nb) {
            const uint2 f = __ldg(wf + nb * 32);
            mma16816(acc + nb * 4, af, f.x, f.y);
        }
    }

    // ---- h1 = relu(acc + b1), packed into A-fragment registers ----
    uint32_t hlo[8], hhi[8];
    #pragma unroll
    for (int nb = 0; nb < 8; ++nb) {
        const int n = nb * 8 + (lane & 3) * 2;
        const float ba = __ldg(b1 + n), bb = __ldg(b1 + n + 1);
        hlo[nb] = pkh(__float2half_rn(fmaxf(acc[nb * 4 + 0] + ba, 0.f)),
                      __float2half_rn(fmaxf(acc[nb * 4 + 1] + bb, 0.f)));
        hhi[nb] = pkh(__float2half_rn(fmaxf(acc[nb * 4 + 2] + ba, 0.f)),
                      __float2half_rn(fmaxf(acc[nb * 4 + 3] + bb, 0.f)));
    }

    // ---- layer-2 GEMM (K=64), A from registers, main + residual B ----
    float ac2[32];
    #pragma unroll
    for (int i = 0; i < 32; ++i) ac2[i] = 0.f;
    #pragma unroll
    for (int s = 0; s < NSTEP2; ++s) {
        const uint32_t ar[4] = { hlo[2 * s], hhi[2 * s], hlo[2 * s + 1], hhi[2 * s + 1] };
        const uint4* wf = g_w2f + (size_t)s * 256 + lane;
        #pragma unroll
        for (int nb = 0; nb < 8; ++nb) {
            const uint4 f = __ldg(wf + nb * 32);
            mma16816(ac2 + nb * 4, ar, f.x, f.y);
            mma16816(ac2 + nb * 4, ar, f.z, f.w);
        }
    }

    // ---- epilogue: out = relu(ac2 + b2) . w3 + b3 ----
    {
        const float b3v = __ldg(b3);
        float pA = 0.f, pB = 0.f;
        #pragma unroll
        for (int nb = 0; nb < 8; ++nb) {
            const int n = nb * 8 + (lane & 3) * 2;
            const float ba = __ldg(b2 + n), bb = __ldg(b2 + n + 1);
            const float wa = g_w3[n],       wb = g_w3[n + 1];
            pA += fmaxf(ac2[nb * 4 + 0] + ba, 0.f) * wa
                + fmaxf(ac2[nb * 4 + 1] + bb, 0.f) * wb;
            pB += fmaxf(ac2[nb * 4 + 2] + ba, 0.f) * wa
                + fmaxf(ac2[nb * 4 + 3] + bb, 0.f) * wb;
        }
        pA += __shfl_xor_sync(0xffffffffu, pA, 1);
        pA += __shfl_xor_sync(0xffffffffu, pA, 2);
        pB += __shfl_xor_sync(0xffffffffu, pB, 1);
        pB += __shfl_xor_sync(0xffffffffu, pB, 2);
        if ((lane & 3) == 0) {
            const int rA = row0 + w * 16 + (lane >> 2);
            if (rA < batch)     out[rA]     = pA + b3v;
            if (rA + 8 < batch) out[rA + 8] = pB + b3v;
        }
    }
}

// ---------------------------------------------------------------------------
extern "C" void kernel_launch(void* const* d_in, const int* in_sizes, int n_in,
                              void* d_out, int out_size)
{
    const float* x    = (const float*)d_in[0];
    const int*   idx1 = (const int*)  d_in[1];
    const float* val1 = (const float*)d_in[2];
    const float* b1   = (const float*)d_in[3];
    const int*   idx2 = (const int*)  d_in[4];
    const float* val2 = (const float*)d_in[5];
    const float* b2   = (const float*)d_in[6];
    const int*   idx3 = (const int*)  d_in[7];
    const float* val3 = (const float*)d_in[8];
    const float* b3   = (const float*)d_in[9];

    const int nnz1  = in_sizes[1] / 2;
    const int nnz2  = in_sizes[4] / 2;
    const int nnz3  = in_sizes[7] / 2;
    const int batch = in_sizes[0] / IN_F;

    const int smem_bytes = DEPTH * CHUNK_B;   // 65536
    cudaFuncSetAttribute(mma_kernel, cudaFuncAttributeMaxDynamicSharedMemorySize, smem_bytes);

    zero_kernel<<<64, 256>>>();
    scatter_kernel<<<32, 256>>>(idx1, val1, nnz1, idx2, val2, nnz2, idx3, val3, nnz3);
    pack_kernel<<<NSTEP1 + 1, 256>>>();

    const int blocks = (batch + MTILE - 1) / MTILE;
    mma_kernel<<<blocks, THREADS, smem_bytes>>>(x, b1, b2, b3, (float*)d_out, batch);
}

// round 14
// speedup vs baseline: 1.1494x; 1.1494x over previous
#include <cuda_runtime.h>
#include <cuda_fp16.h>
#include <stdint.h>

#define IN_F    768
#define HID     64
#define MTILE   256
#define THREADS 256
#define NCHUNK1 24           // 24 chunks of K=32 for layer 1
#define NSTEP2  4            // 64/16 for layer 2
#define DEPTH   3            // cp.async ring depth (3 x 32KB = 96KB)
#define CHUNK_B 32768        // 256 rows x 32 K x 4B (128B per row)

// ---------------- device scratch (no allocations allowed) ----------------
__device__ float g_w1d[HID * IN_F];            // dense W1^T [n][k]
__device__ float g_w2d[HID * HID];             // dense W2^T [n][k]
__device__ uint2 g_w1m[48 * 8 * 32];           // W1 B-fragments per k-step, main only
__device__ uint4 g_w2f[NSTEP2 * 8 * 32];       // W2 B-fragments main+residual
__device__ float g_w3[HID];

static __device__ __forceinline__ void mma16816(float* d, const uint32_t* a,
                                                uint32_t b0, uint32_t b1) {
    asm volatile(
        "mma.sync.aligned.m16n8k16.row.col.f32.f16.f16.f32 "
        "{%0,%1,%2,%3}, {%4,%5,%6,%7}, {%8,%9}, {%0,%1,%2,%3};"
        : "+f"(d[0]), "+f"(d[1]), "+f"(d[2]), "+f"(d[3])
        : "r"(a[0]), "r"(a[1]), "r"(a[2]), "r"(a[3]), "r"(b0), "r"(b1));
}
static __device__ __forceinline__ uint32_t pkh(__half a, __half b) {
    __half2 h = __halves2half2(a, b);
    return *reinterpret_cast<uint32_t*>(&h);
}
static __device__ __forceinline__ uint32_t pk2(float2 v) {
    __half2 h = __floats2half2_rn(v.x, v.y);
    return *reinterpret_cast<uint32_t*>(&h);
}
static __device__ __forceinline__ void cp_async16(uint32_t daddr, const void* src, int srcsz) {
    asm volatile("cp.async.cg.shared.global [%0], [%1], 16, %2;"
                 :: "r"(daddr), "l"(src), "r"(srcsz) : "memory");
}
static __device__ __forceinline__ void cp_commit() {
    asm volatile("cp.async.commit_group;" ::: "memory");
}
template <int N>
static __device__ __forceinline__ void cp_wait() {
    asm volatile("cp.async.wait_group %0;" :: "n"(N) : "memory");
}

// ---------------- prep: zero -> scatter -> pack fragments ----------------
__global__ void zero_kernel() {
    const int t = blockIdx.x * blockDim.x + threadIdx.x;
    const int n = gridDim.x * blockDim.x;
    for (int i = t; i < HID * IN_F; i += n) g_w1d[i] = 0.f;
    for (int i = t; i < HID * HID;  i += n) g_w2d[i] = 0.f;
    for (int i = t; i < HID;        i += n) g_w3[i]  = 0.f;
}

__global__ void scatter_kernel(const int* __restrict__ idx1, const float* __restrict__ val1, int nnz1,
                               const int* __restrict__ idx2, const float* __restrict__ val2, int nnz2,
                               const int* __restrict__ idx3, const float* __restrict__ val3, int nnz3)
{
    const int t = blockIdx.x * blockDim.x + threadIdx.x;
    const int n = gridDim.x * blockDim.x;
    // idx layout [2,nnz]: rows then cols. dense is [n(col)][k(row)].
    for (int i = t; i < nnz1; i += n)
        atomicAdd(&g_w1d[idx1[nnz1 + i] * IN_F + idx1[i]], val1[i]);
    for (int i = t; i < nnz2; i += n)
        atomicAdd(&g_w2d[idx2[nnz2 + i] * HID + idx2[i]], val2[i]);
    for (int i = t; i < nnz3; i += n)
        atomicAdd(&g_w3[idx3[i]], val3[i]);
}

__global__ void pack_kernel() {
    const int tid = threadIdx.x;
    if (blockIdx.x < 48) {                     // one block per k-step of W1 (main only)
        const int s    = blockIdx.x;
        const int nb   = tid >> 5;
        const int lane = tid & 31;
        const int k0 = s * 16 + (lane & 3) * 2;
        const int n  = nb * 8 + (lane >> 2);
        const float m0 = g_w1d[n * IN_F + k0];
        const float m1 = g_w1d[n * IN_F + k0 + 1];
        const float m2 = g_w1d[n * IN_F + k0 + 8];
        const float m3 = g_w1d[n * IN_F + k0 + 9];
        uint2 u;
        u.x = pkh(__float2half_rn(m0), __float2half_rn(m1));
        u.y = pkh(__float2half_rn(m2), __float2half_rn(m3));
        g_w1m[(s * 8 + nb) * 32 + lane] = u;
    } else {                                   // last block packs all of W2 (main+resid)
        for (int j = tid; j < NSTEP2 * 8 * 32; j += 256) {
            const int s    = j >> 8;
            const int nb   = (j >> 5) & 7;
            const int lane = j & 31;
            const int k0 = s * 16 + (lane & 3) * 2;
            const int n  = nb * 8 + (lane >> 2);
            const float m0 = g_w2d[n * HID + k0];
            const float m1 = g_w2d[n * HID + k0 + 1];
            const float m2 = g_w2d[n * HID + k0 + 8];
            const float m3 = g_w2d[n * HID + k0 + 9];
            const __half h0 = __float2half_rn(m0), h1 = __float2half_rn(m1);
            const __half h2 = __float2half_rn(m2), h3 = __float2half_rn(m3);
            uint4 u;
            u.x = pkh(h0, h1);
            u.y = pkh(h2, h3);
            u.z = pkh(__float2half_rn(m0 - __half2float(h0)), __float2half_rn(m1 - __half2float(h1)));
            u.w = pkh(__float2half_rn(m2 - __half2float(h2)), __float2half_rn(m3 - __half2float(h3)));
            g_w2f[(s * 8 + nb) * 32 + lane] = u;
        }
    }
}

// ---------------------------------------------------------------------------
// Main kernel (R12 base, R14 deltas): K=32 chunks (24 barriers instead of 48,
// 2 k-steps of MMA per barrier) in a 3-deep ring, and a (cu + 2*row)&7 XOR
// swizzle of 16B units inside each 128B row making every A-fragment LDS.64
// phase conflict-free (16 distinct bank-pairs). Main-only W1, residual W2,
// register-resident h1. 96KB smem -> 2 CTAs/SM.
// ---------------------------------------------------------------------------
extern __shared__ __align__(16) unsigned char smem[];

__global__ __launch_bounds__(THREADS, 2)
void mma_kernel(const float* __restrict__ x,
                const float* __restrict__ b1,
                const float* __restrict__ b2,
                const float* __restrict__ b3,
                float* __restrict__ out, int batch)
{
    uint32_t sb;
    asm("{ .reg .u64 t; cvta.to.shared.u64 t, %1; cvt.u32.u64 %0, t; }" : "=r"(sb) : "l"(smem));
    const int tid  = threadIdx.x;
    const int w    = tid >> 5;
    const int lane = tid & 31;
    const int row0 = blockIdx.x * MTILE;
    const bool full = (row0 + MTILE) <= batch;

    // ---- cp.async issue of one 32-K chunk: 16B copies, 8 per thread ----
    const int crow = tid >> 3;        // 0..31 (row within a 32-row pass)
    const int cu   = tid & 7;         // 16B unit within the 128B row
    auto issue = [&](int c) {
        const uint32_t dbase = sb + (uint32_t)(c % DEPTH) * CHUNK_B;
        #pragma unroll
        for (int j = 0; j < 8; ++j) {
            const int row = j * 32 + crow;
            const int ok = (full || (row0 + row) < batch) ? 16 : 0;
            const float* src = x + (size_t)(row0 + row) * IN_F + c * 32 + cu * 4;
            cp_async16(dbase + (uint32_t)(row * 128 + (((cu + 2 * row) & 7) << 4)), src, ok);
        }
        cp_commit();
    };

    // A-fragment geometry: stripe rows, swizzled 16B units
    const int u    = lane & 3;
    const int u2   = u >> 1;
    const int uodd = (u & 1) << 3;      // 8B half within the 16B unit
    const int R0   = w * 16 + (lane >> 2);       // stripe0 frag row
    const int R1   = R0 + 128;                   // stripe1 frag row

    float acc0[32], acc1[32];
    #pragma unroll
    for (int i = 0; i < 32; ++i) { acc0[i] = 0.f; acc1[i] = 0.f; }

    // ---- prologue: 2 chunks in flight ----
    issue(0); issue(1);

    // ---- layer-1 mainloop over 24 chunks: ONE barrier per chunk ----
    #pragma unroll 1
    for (int c = 0; c < NCHUNK1; ++c) {
        cp_wait<1>();                 // this thread's chunk-c copies landed
        __syncthreads();              // chunk-c visible; all warps done with c-1
        if (c + 2 < NCHUNK1) issue(c + 2);   // refills slot (c-1)%3 — WAR-safe

        const uint32_t xb = sb + (uint32_t)(c % DEPTH) * CHUNK_B;

        #pragma unroll
        for (int i = 0; i < 2; ++i) {
            uint32_t af[8];
            {
                float2 v;
                const int cuA = i * 4 + u2;          // 16B unit of k-cols [i*16 + u*2]
                const int cuB = cuA + 2;             // +8 floats
                const uint32_t aA0 = xb + (uint32_t)(R0 * 128 + (((cuA + 2 * R0) & 7) << 4) + uodd);
                const uint32_t aA1 = xb + (uint32_t)((R0 + 8) * 128 + (((cuA + 2 * (R0 + 8)) & 7) << 4) + uodd);
                const uint32_t aA2 = xb + (uint32_t)(R0 * 128 + (((cuB + 2 * R0) & 7) << 4) + uodd);
                const uint32_t aA3 = xb + (uint32_t)((R0 + 8) * 128 + (((cuB + 2 * (R0 + 8)) & 7) << 4) + uodd);
                const uint32_t aB0 = xb + (uint32_t)(R1 * 128 + (((cuA + 2 * R1) & 7) << 4) + uodd);
                const uint32_t aB1 = xb + (uint32_t)((R1 + 8) * 128 + (((cuA + 2 * (R1 + 8)) & 7) << 4) + uodd);
                const uint32_t aB2 = xb + (uint32_t)(R1 * 128 + (((cuB + 2 * R1) & 7) << 4) + uodd);
                const uint32_t aB3 = xb + (uint32_t)((R1 + 8) * 128 + (((cuB + 2 * (R1 + 8)) & 7) << 4) + uodd);
                asm volatile("ld.shared.v2.f32 {%0,%1}, [%2];" : "=f"(v.x), "=f"(v.y) : "r"(aA0));
                af[0] = pk2(v);
                asm volatile("ld.shared.v2.f32 {%0,%1}, [%2];" : "=f"(v.x), "=f"(v.y) : "r"(aA1));
                af[1] = pk2(v);
                asm volatile("ld.shared.v2.f32 {%0,%1}, [%2];" : "=f"(v.x), "=f"(v.y) : "r"(aA2));
                af[2] = pk2(v);
                asm volatile("ld.shared.v2.f32 {%0,%1}, [%2];" : "=f"(v.x), "=f"(v.y) : "r"(aA3));
                af[3] = pk2(v);
                asm volatile("ld.shared.v2.f32 {%0,%1}, [%2];" : "=f"(v.x), "=f"(v.y) : "r"(aB0));
                af[4] = pk2(v);
                asm volatile("ld.shared.v2.f32 {%0,%1}, [%2];" : "=f"(v.x), "=f"(v.y) : "r"(aB1));
                af[5] = pk2(v);
                asm volatile("ld.shared.v2.f32 {%0,%1}, [%2];" : "=f"(v.x), "=f"(v.y) : "r"(aB2));
                af[6] = pk2(v);
                asm volatile("ld.shared.v2.f32 {%0,%1}, [%2];" : "=f"(v.x), "=f"(v.y) : "r"(aB3));
                af[7] = pk2(v);
            }

            const uint2* wf = g_w1m + (size_t)(c * 2 + i) * 256 + lane;
            #pragma unroll
            for (int nb = 0; nb < 8; ++nb) {
                const uint2 f = __ldg(wf + nb * 32);
                mma16816(acc0 + nb * 4, af,     f.x, f.y);
                mma16816(acc1 + nb * 4, af + 4, f.x, f.y);
            }
        }
    }

    // ---- h1 = relu(acc + b1), packed into A-fragment registers ----
    uint32_t hlo0[8], hhi0[8], hlo1[8], hhi1[8];
    #pragma unroll
    for (int nb = 0; nb < 8; ++nb) {
        const int n = nb * 8 + (lane & 3) * 2;
        const float ba = __ldg(b1 + n), bb = __ldg(b1 + n + 1);
        hlo0[nb] = pkh(__float2half_rn(fmaxf(acc0[nb * 4 + 0] + ba, 0.f)),
                       __float2half_rn(fmaxf(acc0[nb * 4 + 1] + bb, 0.f)));
        hhi0[nb] = pkh(__float2half_rn(fmaxf(acc0[nb * 4 + 2] + ba, 0.f)),
                       __float2half_rn(fmaxf(acc0[nb * 4 + 3] + bb, 0.f)));
        hlo1[nb] = pkh(__float2half_rn(fmaxf(acc1[nb * 4 + 0] + ba, 0.f)),
                       __float2half_rn(fmaxf(acc1[nb * 4 + 1] + bb, 0.f)));
        hhi1[nb] = pkh(__float2half_rn(fmaxf(acc1[nb * 4 + 2] + ba, 0.f)),
                       __float2half_rn(fmaxf(acc1[nb * 4 + 3] + bb, 0.f)));
    }

    // ---- layer-2 GEMM (K=64), A from registers, main + residual B ----
    float ac20[32], ac21[32];
    #pragma unroll
    for (int i = 0; i < 32; ++i) { ac20[i] = 0.f; ac21[i] = 0.f; }
    #pragma unroll
    for (int s = 0; s < NSTEP2; ++s) {
        const uint32_t a0r[4] = { hlo0[2 * s], hhi0[2 * s], hlo0[2 * s + 1], hhi0[2 * s + 1] };
        const uint32_t a1r[4] = { hlo1[2 * s], hhi1[2 * s], hlo1[2 * s + 1], hhi1[2 * s + 1] };
        const uint4* wf = g_w2f + (size_t)s * 256 + lane;
        #pragma unroll
        for (int nb = 0; nb < 8; ++nb) {
            const uint4 f = __ldg(wf + nb * 32);
            mma16816(ac20 + nb * 4, a0r, f.x, f.y);
            mma16816(ac20 + nb * 4, a0r, f.z, f.w);
            mma16816(ac21 + nb * 4, a1r, f.x, f.y);
            mma16816(ac21 + nb * 4, a1r, f.z, f.w);
        }
    }

    // ---- epilogue: out = relu(ac2 + b2) . w3 + b3 ----
    {
        const float b3v = __ldg(b3);
        #pragma unroll
        for (int st = 0; st < 2; ++st) {
            const float* ac = st ? ac21 : ac20;
            float pA = 0.f, pB = 0.f;
            #pragma unroll
            for (int nb = 0; nb < 8; ++nb) {
                const int n = nb * 8 + (lane & 3) * 2;
                const float ba = __ldg(b2 + n), bb = __ldg(b2 + n + 1);
                const float wa = g_w3[n],       wb = g_w3[n + 1];
                pA += fmaxf(ac[nb * 4 + 0] + ba, 0.f) * wa
                    + fmaxf(ac[nb * 4 + 1] + bb, 0.f) * wb;
                pB += fmaxf(ac[nb * 4 + 2] + ba, 0.f) * wa
                    + fmaxf(ac[nb * 4 + 3] + bb, 0.f) * wb;
            }
            pA += __shfl_xor_sync(0xffffffffu, pA, 1);
            pA += __shfl_xor_sync(0xffffffffu, pA, 2);
            pB += __shfl_xor_sync(0xffffffffu, pB, 1);
            pB += __shfl_xor_sync(0xffffffffu, pB, 2);
            if ((lane & 3) == 0) {
                const int rA = row0 + st * 128 + w * 16 + (lane >> 2);
                if (rA < batch)     out[rA]     = pA + b3v;
                if (rA + 8 < batch) out[rA + 8] = pB + b3v;
            }
        }
    }
}

// ---------------------------------------------------------------------------
extern "C" void kernel_launch(void* const* d_in, const int* in_sizes, int n_in,
                              void* d_out, int out_size)
{
    const float* x    = (const float*)d_in[0];
    const int*   idx1 = (const int*)  d_in[1];
    const float* val1 = (const float*)d_in[2];
    const float* b1   = (const float*)d_in[3];
    const int*   idx2 = (const int*)  d_in[4];
    const float* val2 = (const float*)d_in[5];
    const float* b2   = (const float*)d_in[6];
    const int*   idx3 = (const int*)  d_in[7];
    const float* val3 = (const float*)d_in[8];
    const float* b3   = (const float*)d_in[9];

    const int nnz1  = in_sizes[1] / 2;
    const int nnz2  = in_sizes[4] / 2;
    const int nnz3  = in_sizes[7] / 2;
    const int batch = in_sizes[0] / IN_F;

    const int smem_bytes = DEPTH * CHUNK_B;   // 98304
    cudaFuncSetAttribute(mma_kernel, cudaFuncAttributeMaxDynamicSharedMemorySize, smem_bytes);

    zero_kernel<<<64, 256>>>();
    scatter_kernel<<<32, 256>>>(idx1, val1, nnz1, idx2, val2, nnz2, idx3, val3, nnz3);
    pack_kernel<<<49, 256>>>();

    const int blocks = (batch + MTILE - 1) / MTILE;
    mma_kernel<<<blocks, THREADS, smem_bytes>>>(x, b1, b2, b3, (float*)d_out, batch);
}

// round 15
// speedup vs baseline: 1.3486x; 1.1733x over previous
#include <cuda_runtime.h>
#include <cuda_fp16.h>
#include <stdint.h>

#define IN_F    768
#define HID     64
#define MTILE   256
#define THREADS 256
#define NSTEP1  48           // 768/16 k-steps for layer 1 (= chunks)
#define NSTEP2  4            // 64/16 for layer 2
#define DEPTH   4            // cp.async ring depth
#define CHUNK_B 16384        // 256 rows x 16 K x 4B (64B per row)

// ---------------- device scratch (no allocations allowed) ----------------
__device__ float g_w1d[HID * IN_F];            // dense W1^T [n][k]
__device__ float g_w2d[HID * HID];             // dense W2^T [n][k]
__device__ uint2 g_w1m[NSTEP1 * 8 * 32];       // W1 B-fragments, main only (b0,b1)
__device__ uint4 g_w2f[NSTEP2 * 8 * 32];       // W2 B-fragments main+residual
__device__ float g_w3[HID];

static __device__ __forceinline__ void mma16816(float* d, const uint32_t* a,
                                                uint32_t b0, uint32_t b1) {
    asm volatile(
        "mma.sync.aligned.m16n8k16.row.col.f32.f16.f16.f32 "
        "{%0,%1,%2,%3}, {%4,%5,%6,%7}, {%8,%9}, {%0,%1,%2,%3};"
        : "+f"(d[0]), "+f"(d[1]), "+f"(d[2]), "+f"(d[3])
        : "r"(a[0]), "r"(a[1]), "r"(a[2]), "r"(a[3]), "r"(b0), "r"(b1));
}
static __device__ __forceinline__ uint32_t pkh(__half a, __half b) {
    __half2 h = __halves2half2(a, b);
    return *reinterpret_cast<uint32_t*>(&h);
}
static __device__ __forceinline__ uint32_t pk2(float2 v) {
    __half2 h = __floats2half2_rn(v.x, v.y);
    return *reinterpret_cast<uint32_t*>(&h);
}
static __device__ __forceinline__ void cp_async16(uint32_t daddr, const void* src, int srcsz) {
    asm volatile("cp.async.cg.shared.global [%0], [%1], 16, %2;"
                 :: "r"(daddr), "l"(src), "r"(srcsz) : "memory");
}
static __device__ __forceinline__ void cp_commit() {
    asm volatile("cp.async.commit_group;" ::: "memory");
}
template <int N>
static __device__ __forceinline__ void cp_wait() {
    asm volatile("cp.async.wait_group %0;" :: "n"(N) : "memory");
}

// ---------------- prep: zero -> scatter -> pack fragments ----------------
__global__ void zero_kernel() {
    const int t = blockIdx.x * blockDim.x + threadIdx.x;
    const int n = gridDim.x * blockDim.x;
    for (int i = t; i < HID * IN_F; i += n) g_w1d[i] = 0.f;
    for (int i = t; i < HID * HID;  i += n) g_w2d[i] = 0.f;
    for (int i = t; i < HID;        i += n) g_w3[i]  = 0.f;
}

__global__ void scatter_kernel(const int* __restrict__ idx1, const float* __restrict__ val1, int nnz1,
                               const int* __restrict__ idx2, const float* __restrict__ val2, int nnz2,
                               const int* __restrict__ idx3, const float* __restrict__ val3, int nnz3)
{
    const int t = blockIdx.x * blockDim.x + threadIdx.x;
    const int n = gridDim.x * blockDim.x;
    // idx layout [2,nnz]: rows then cols. dense is [n(col)][k(row)].
    for (int i = t; i < nnz1; i += n)
        atomicAdd(&g_w1d[idx1[nnz1 + i] * IN_F + idx1[i]], val1[i]);
    for (int i = t; i < nnz2; i += n)
        atomicAdd(&g_w2d[idx2[nnz2 + i] * HID + idx2[i]], val2[i]);
    for (int i = t; i < nnz3; i += n)
        atomicAdd(&g_w3[idx3[i]], val3[i]);
}

__global__ void pack_kernel() {
    const int tid = threadIdx.x;
    if (blockIdx.x < NSTEP1) {                 // one block per k-step of W1 (main only)
        const int s    = blockIdx.x;
        const int nb   = tid >> 5;
        const int lane = tid & 31;
        const int k0 = s * 16 + (lane & 3) * 2;
        const int n  = nb * 8 + (lane >> 2);
        const float m0 = g_w1d[n * IN_F + k0];
        const float m1 = g_w1d[n * IN_F + k0 + 1];
        const float m2 = g_w1d[n * IN_F + k0 + 8];
        const float m3 = g_w1d[n * IN_F + k0 + 9];
        uint2 u;
        u.x = pkh(__float2half_rn(m0), __float2half_rn(m1));
        u.y = pkh(__float2half_rn(m2), __float2half_rn(m3));
        g_w1m[(s * 8 + nb) * 32 + lane] = u;
    } else {                                   // last block packs all of W2 (main+resid)
        for (int j = tid; j < NSTEP2 * 8 * 32; j += 256) {
            const int s    = j >> 8;
            const int nb   = (j >> 5) & 7;
            const int lane = j & 31;
            const int k0 = s * 16 + (lane & 3) * 2;
            const int n  = nb * 8 + (lane >> 2);
            const float m0 = g_w2d[n * HID + k0];
            const float m1 = g_w2d[n * HID + k0 + 1];
            const float m2 = g_w2d[n * HID + k0 + 8];
            const float m3 = g_w2d[n * HID + k0 + 9];
            const __half h0 = __float2half_rn(m0), h1 = __float2half_rn(m1);
            const __half h2 = __float2half_rn(m2), h3 = __float2half_rn(m3);
            uint4 u;
            u.x = pkh(h0, h1);
            u.y = pkh(h2, h3);
            u.z = pkh(__float2half_rn(m0 - __half2float(h0)), __float2half_rn(m1 - __half2float(h1)));
            u.w = pkh(__float2half_rn(m2 - __half2float(h2)), __float2half_rn(m3 - __half2float(h3)));
            g_w2f[(s * 8 + nb) * 32 + lane] = u;
        }
    }
}

// ---------------------------------------------------------------------------
// Main kernel: R12 pipeline (16K chunks, DEPTH-4 ring, 3 in flight, one
// barrier/chunk) + R15 delta: XOR swizzle of 16B units by row, phys_unit =
// (unit + row) & 3, on both the cp.async store and the A-fragment loads ->
// every LDS.64 is 2-phase conflict-free (16 distinct bank-pairs per
// half-warp, enumerated). Main-only W1, residual W2, register h1.
// ---------------------------------------------------------------------------
extern __shared__ __align__(16) unsigned char smem[];

__global__ __launch_bounds__(THREADS, 2)
void mma_kernel(const float* __restrict__ x,
                const float* __restrict__ b1,
                const float* __restrict__ b2,
                const float* __restrict__ b3,
                float* __restrict__ out, int batch)
{
    uint32_t sb;
    asm("{ .reg .u64 t; cvta.to.shared.u64 t, %1; cvt.u32.u64 %0, t; }" : "=r"(sb) : "l"(smem));
    const int tid  = threadIdx.x;
    const int w    = tid >> 5;
    const int lane = tid & 31;
    const int row0 = blockIdx.x * MTILE;
    const bool full = (row0 + MTILE) <= batch;

    // ---- cp.async issue of one 16-K chunk: 16B copies, 4 per thread ----
    const int crow = tid >> 2;        // 0..63 (row within a 64-row pass)
    const int cu   = tid & 3;         // 16B unit within the 64B row piece
    auto issue = [&](int c) {
        const uint32_t dbase = sb + (uint32_t)(c & (DEPTH - 1)) * CHUNK_B;
        #pragma unroll
        for (int j = 0; j < 4; ++j) {
            const int row = j * 64 + crow;
            const int ok = (full || (row0 + row) < batch) ? 16 : 0;
            const float* src = x + (size_t)(row0 + row) * IN_F + c * 16 + cu * 4;
            cp_async16(dbase + (uint32_t)(row * 64 + (((cu + row) & 3) << 4)), src, ok);
        }
        cp_commit();
    };

    // A-fragment geometry: swizzled 16B units within 64B rows
    const int u    = lane & 3;
    const int unit = u >> 1;            // base 16B unit (0 or 1)
    const int uodd = (u & 1) << 3;      // 8B half within the 16B unit
    const int R0   = w * 16 + (lane >> 2);       // stripe0 frag row
    const int R1   = R0 + 128;                   // stripe1 frag row

    float acc0[32], acc1[32];
    #pragma unroll
    for (int i = 0; i < 32; ++i) { acc0[i] = 0.f; acc1[i] = 0.f; }

    // ---- prologue: 3 chunks in flight ----
    issue(0); issue(1); issue(2);

    // ---- layer-1 mainloop over 48 chunks: ONE barrier per chunk ----
    #pragma unroll 1
    for (int c = 0; c < NSTEP1; ++c) {
        cp_wait<2>();                 // this thread's chunk-c copies landed
        __syncthreads();              // chunk-c visible; all warps done with c-1
        if (c + 3 < NSTEP1) issue(c + 3);   // refills slot (c-1)&3 — WAR-safe

        const uint32_t xb = sb + (uint32_t)(c & (DEPTH - 1)) * CHUNK_B;
        uint32_t af[8];
        {
            float2 v;
            const uint32_t a0 = xb + (uint32_t)(R0 * 64        + (((unit     + R0)     & 3) << 4) + uodd);
            const uint32_t a1 = xb + (uint32_t)((R0 + 8) * 64  + (((unit     + R0 + 8) & 3) << 4) + uodd);
            const uint32_t a2 = xb + (uint32_t)(R0 * 64        + (((unit + 2 + R0)     & 3) << 4) + uodd);
            const uint32_t a3 = xb + (uint32_t)((R0 + 8) * 64  + (((unit + 2 + R0 + 8) & 3) << 4) + uodd);
            const uint32_t a4 = xb + (uint32_t)(R1 * 64        + (((unit     + R1)     & 3) << 4) + uodd);
            const uint32_t a5 = xb + (uint32_t)((R1 + 8) * 64  + (((unit     + R1 + 8) & 3) << 4) + uodd);
            const uint32_t a6 = xb + (uint32_t)(R1 * 64        + (((unit + 2 + R1)     & 3) << 4) + uodd);
            const uint32_t a7 = xb + (uint32_t)((R1 + 8) * 64  + (((unit + 2 + R1 + 8) & 3) << 4) + uodd);
            asm volatile("ld.shared.v2.f32 {%0,%1}, [%2];" : "=f"(v.x), "=f"(v.y) : "r"(a0));
            af[0] = pk2(v);
            asm volatile("ld.shared.v2.f32 {%0,%1}, [%2];" : "=f"(v.x), "=f"(v.y) : "r"(a1));
            af[1] = pk2(v);
            asm volatile("ld.shared.v2.f32 {%0,%1}, [%2];" : "=f"(v.x), "=f"(v.y) : "r"(a2));
            af[2] = pk2(v);
            asm volatile("ld.shared.v2.f32 {%0,%1}, [%2];" : "=f"(v.x), "=f"(v.y) : "r"(a3));
            af[3] = pk2(v);
            asm volatile("ld.shared.v2.f32 {%0,%1}, [%2];" : "=f"(v.x), "=f"(v.y) : "r"(a4));
            af[4] = pk2(v);
            asm volatile("ld.shared.v2.f32 {%0,%1}, [%2];" : "=f"(v.x), "=f"(v.y) : "r"(a5));
            af[5] = pk2(v);
            asm volatile("ld.shared.v2.f32 {%0,%1}, [%2];" : "=f"(v.x), "=f"(v.y) : "r"(a6));
            af[6] = pk2(v);
            asm volatile("ld.shared.v2.f32 {%0,%1}, [%2];" : "=f"(v.x), "=f"(v.y) : "r"(a7));
            af[7] = pk2(v);
        }

        const uint2* wf = g_w1m + (size_t)c * 256 + lane;
        #pragma unroll
        for (int nb = 0; nb < 8; ++nb) {
            const uint2 f = __ldg(wf + nb * 32);
            mma16816(acc0 + nb * 4, af,     f.x, f.y);
            mma16816(acc1 + nb * 4, af + 4, f.x, f.y);
        }
    }

    // ---- h1 = relu(acc + b1), packed into A-fragment registers ----
    uint32_t hlo0[8], hhi0[8], hlo1[8], hhi1[8];
    #pragma unroll
    for (int nb = 0; nb < 8; ++nb) {
        const int n = nb * 8 + (lane & 3) * 2;
        const float ba = __ldg(b1 + n), bb = __ldg(b1 + n + 1);
        hlo0[nb] = pkh(__float2half_rn(fmaxf(acc0[nb * 4 + 0] + ba, 0.f)),
                       __float2half_rn(fmaxf(acc0[nb * 4 + 1] + bb, 0.f)));
        hhi0[nb] = pkh(__float2half_rn(fmaxf(acc0[nb * 4 + 2] + ba, 0.f)),
                       __float2half_rn(fmaxf(acc0[nb * 4 + 3] + bb, 0.f)));
        hlo1[nb] = pkh(__float2half_rn(fmaxf(acc1[nb * 4 + 0] + ba, 0.f)),
                       __float2half_rn(fmaxf(acc1[nb * 4 + 1] + bb, 0.f)));
        hhi1[nb] = pkh(__float2half_rn(fmaxf(acc1[nb * 4 + 2] + ba, 0.f)),
                       __float2half_rn(fmaxf(acc1[nb * 4 + 3] + bb, 0.f)));
    }

    // ---- layer-2 GEMM (K=64), A from registers, main + residual B ----
    float ac20[32], ac21[32];
    #pragma unroll
    for (int i = 0; i < 32; ++i) { ac20[i] = 0.f; ac21[i] = 0.f; }
    #pragma unroll
    for (int s = 0; s < NSTEP2; ++s) {
        const uint32_t a0r[4] = { hlo0[2 * s], hhi0[2 * s], hlo0[2 * s + 1], hhi0[2 * s + 1] };
        const uint32_t a1r[4] = { hlo1[2 * s], hhi1[2 * s], hlo1[2 * s + 1], hhi1[2 * s + 1] };
        const uint4* wf = g_w2f + (size_t)s * 256 + lane;
        #pragma unroll
        for (int nb = 0; nb < 8; ++nb) {
            const uint4 f = __ldg(wf + nb * 32);
            mma16816(ac20 + nb * 4, a0r, f.x, f.y);
            mma16816(ac20 + nb * 4, a0r, f.z, f.w);
            mma16816(ac21 + nb * 4, a1r, f.x, f.y);
            mma16816(ac21 + nb * 4, a1r, f.z, f.w);
        }
    }

    // ---- epilogue: out = relu(ac2 + b2) . w3 + b3 ----
    {
        const float b3v = __ldg(b3);
        #pragma unroll
        for (int st = 0; st < 2; ++st) {
            const float* ac = st ? ac21 : ac20;
            float pA = 0.f, pB = 0.f;
            #pragma unroll
            for (int nb = 0; nb < 8; ++nb) {
                const int n = nb * 8 + (lane & 3) * 2;
                const float ba = __ldg(b2 + n), bb = __ldg(b2 + n + 1);
                const float wa = g_w3[n],       wb = g_w3[n + 1];
                pA += fmaxf(ac[nb * 4 + 0] + ba, 0.f) * wa
                    + fmaxf(ac[nb * 4 + 1] + bb, 0.f) * wb;
                pB += fmaxf(ac[nb * 4 + 2] + ba, 0.f) * wa
                    + fmaxf(ac[nb * 4 + 3] + bb, 0.f) * wb;
            }
            pA += __shfl_xor_sync(0xffffffffu, pA, 1);
            pA += __shfl_xor_sync(0xffffffffu, pA, 2);
            pB += __shfl_xor_sync(0xffffffffu, pB, 1);
            pB += __shfl_xor_sync(0xffffffffu, pB, 2);
            if ((lane & 3) == 0) {
                const int rA = row0 + st * 128 + w * 16 + (lane >> 2);
                if (rA < batch)     out[rA]     = pA + b3v;
                if (rA + 8 < batch) out[rA + 8] = pB + b3v;
            }
        }
    }
}

// ---------------------------------------------------------------------------
extern "C" void kernel_launch(void* const* d_in, const int* in_sizes, int n_in,
                              void* d_out, int out_size)
{
    const float* x    = (const float*)d_in[0];
    const int*   idx1 = (const int*)  d_in[1];
    const float* val1 = (const float*)d_in[2];
    const float* b1   = (const float*)d_in[3];
    const int*   idx2 = (const int*)  d_in[4];
    const float* val2 = (const float*)d_in[5];
    const float* b2   = (const float*)d_in[6];
    const int*   idx3 = (const int*)  d_in[7];
    const float* val3 = (const float*)d_in[8];
    const float* b3   = (const float*)d_in[9];

    const int nnz1  = in_sizes[1] / 2;
    const int nnz2  = in_sizes[4] / 2;
    const int nnz3  = in_sizes[7] / 2;
    const int batch = in_sizes[0] / IN_F;

    const int smem_bytes = DEPTH * CHUNK_B;   // 65536
    cudaFuncSetAttribute(mma_kernel, cudaFuncAttributeMaxDynamicSharedMemorySize, smem_bytes);

    zero_kernel<<<64, 256>>>();
    scatter_kernel<<<32, 256>>>(idx1, val1, nnz1, idx2, val2, nnz2, idx3, val3, nnz3);
    pack_kernel<<<NSTEP1 + 1, 256>>>();

    const int blocks = (batch + MTILE - 1) / MTILE;
    mma_kernel<<<blocks, THREADS, smem_bytes>>>(x, b1, b2, b3, (float*)d_out, batch);
}